// round 14
// baseline (speedup 1.0000x reference)
#include <cuda_runtime.h>
#include <math.h>
#include <stdint.h>

#define BB 8
#define TT 2048
#define CC 1024
#define FF 4096
#define NN (BB * TT)   // 16384 rows

// ---------------- scratch (device globals; no allocation allowed) -----------
__device__ float g_xk[NN * CC];
__device__ float g_xv[NN * CC];
__device__ float g_xr[NN * CC];
__device__ float g_k [NN * CC];
__device__ float g_v [NN * CC];
__device__ float g_sr[NN * CC];
__device__ float g_kk[(size_t)NN * FF];
__device__ float g_w [13 * 1024 * 1024];   // tf32-rounded weights

#define WOFF_K   (0 * 1048576)
#define WOFF_V   (1 * 1048576)
#define WOFF_R   (2 * 1048576)
#define WOFF_O   (3 * 1048576)
#define WOFF_KEY (4 * 1048576)
#define WOFF_REC (8 * 1048576)
#define WOFF_VAL (9 * 1048576)

// ---------------- helpers ----------------------------------------------------
__device__ __forceinline__ float to_tf32(float x) {
    uint32_t u;
    asm("cvt.rna.tf32.f32 %0, %1;" : "=r"(u) : "f"(x));
    return __uint_as_float(u);
}

__device__ __forceinline__ uint32_t s2u(const void* p) {
    uint32_t a;
    asm("{ .reg .u64 t; cvta.to.shared.u64 t, %1; cvt.u32.u64 %0, t; }" : "=r"(a) : "l"(p));
    return a;
}

__device__ __forceinline__ void mma_tf32(float* c, const uint32_t* a, const uint32_t* b) {
    asm volatile(
        "mma.sync.aligned.m16n8k8.row.col.f32.tf32.tf32.f32 "
        "{%0,%1,%2,%3}, {%4,%5,%6,%7}, {%8,%9}, {%0,%1,%2,%3};"
        : "+f"(c[0]), "+f"(c[1]), "+f"(c[2]), "+f"(c[3])
        : "r"(a[0]), "r"(a[1]), "r"(a[2]), "r"(a[3]), "r"(b[0]), "r"(b[1]));
}

__device__ __forceinline__ void ldsm_x4(uint32_t addr, uint32_t* r) {
    asm volatile("ldmatrix.sync.aligned.m8n8.x4.shared.b16 {%0,%1,%2,%3}, [%4];"
        : "=r"(r[0]), "=r"(r[1]), "=r"(r[2]), "=r"(r[3]) : "r"(addr));
}

__device__ __forceinline__ void ldsm_x2(uint32_t addr, uint32_t* r) {
    asm volatile("ldmatrix.sync.aligned.m8n8.x2.shared.b16 {%0,%1}, [%2];"
        : "=r"(r[0]), "=r"(r[1]) : "r"(addr));
}

// ---------------- weight tf32 pre-round (single fused kernel) ----------------
__global__ void round_all_kernel(const float* __restrict__ Wk,
                                 const float* __restrict__ Wv,
                                 const float* __restrict__ Wr,
                                 const float* __restrict__ Wo,
                                 const float* __restrict__ Wkey,
                                 const float* __restrict__ Wrec,
                                 const float* __restrict__ Wval,
                                 float* __restrict__ w) {
    const int i = blockIdx.x * blockDim.x + threadIdx.x;   // float4 index
    const int S = 262144;                                   // 1M floats in float4
    const float* src; float* dst; int off;
    if (i < S)            { src = Wk;   dst = w + WOFF_K;   off = i; }
    else if (i < 2 * S)   { src = Wv;   dst = w + WOFF_V;   off = i - S; }
    else if (i < 3 * S)   { src = Wr;   dst = w + WOFF_R;   off = i - 2 * S; }
    else if (i < 4 * S)   { src = Wo;   dst = w + WOFF_O;   off = i - 3 * S; }
    else if (i < 8 * S)   { src = Wkey; dst = w + WOFF_KEY; off = i - 4 * S; }
    else if (i < 9 * S)   { src = Wrec; dst = w + WOFF_REC; off = i - 8 * S; }
    else                  { src = Wval; dst = w + WOFF_VAL; off = i - 9 * S; }
    float4 v = ((const float4*)src)[off];
    v.x = to_tf32(v.x); v.y = to_tf32(v.y);
    v.z = to_tf32(v.z); v.w = to_tf32(v.w);
    ((float4*)dst)[off] = v;
}

// ---------------- fused LayerNorm + token-shift mix ---------------------------
__device__ __forceinline__ void dual_ln_stats(float4 c4, float4 p4,
                                              float& muc, float& invc,
                                              float& mup, float& invp) {
    float sc  = c4.x + c4.y + c4.z + c4.w;
    float sc2 = c4.x * c4.x + c4.y * c4.y + c4.z * c4.z + c4.w * c4.w;
    float sp  = p4.x + p4.y + p4.z + p4.w;
    float sp2 = p4.x * p4.x + p4.y * p4.y + p4.z * p4.z + p4.w * p4.w;

    __shared__ float sh[4][8];
    const int tid = threadIdx.x, wid = tid >> 5, lid = tid & 31;
    #pragma unroll
    for (int o = 16; o > 0; o >>= 1) {
        sc  += __shfl_xor_sync(0xffffffffu, sc,  o);
        sc2 += __shfl_xor_sync(0xffffffffu, sc2, o);
        sp  += __shfl_xor_sync(0xffffffffu, sp,  o);
        sp2 += __shfl_xor_sync(0xffffffffu, sp2, o);
    }
    if (lid == 0) { sh[0][wid] = sc; sh[1][wid] = sc2; sh[2][wid] = sp; sh[3][wid] = sp2; }
    __syncthreads();
    if (wid == 0) {
        float a0 = (lid < 8) ? sh[0][lid] : 0.f;
        float a1 = (lid < 8) ? sh[1][lid] : 0.f;
        float a2 = (lid < 8) ? sh[2][lid] : 0.f;
        float a3 = (lid < 8) ? sh[3][lid] : 0.f;
        #pragma unroll
        for (int o = 4; o > 0; o >>= 1) {
            a0 += __shfl_xor_sync(0xffffffffu, a0, o);
            a1 += __shfl_xor_sync(0xffffffffu, a1, o);
            a2 += __shfl_xor_sync(0xffffffffu, a2, o);
            a3 += __shfl_xor_sync(0xffffffffu, a3, o);
        }
        if (lid == 0) { sh[0][0] = a0; sh[1][0] = a1; sh[2][0] = a2; sh[3][0] = a3; }
    }
    __syncthreads();
    muc = sh[0][0] * (1.0f / CC);
    float varc = fmaxf(sh[1][0] * (1.0f / CC) - muc * muc, 0.f);
    invc = rsqrtf(varc + 1e-5f);
    mup = sh[2][0] * (1.0f / CC);
    float varp = fmaxf(sh[3][0] * (1.0f / CC) - mup * mup, 0.f);
    invp = rsqrtf(varp + 1e-5f);
}

__device__ __forceinline__ float4 ln4(float4 v, float mu, float inv, float4 w, float4 b) {
    float4 r;
    r.x = (v.x - mu) * inv * w.x + b.x;
    r.y = (v.y - mu) * inv * w.y + b.y;
    r.z = (v.z - mu) * inv * w.z + b.z;
    r.w = (v.w - mu) * inv * w.w + b.w;
    return r;
}

__device__ __forceinline__ float4 mixf4(float4 h, float4 p, float4 m) {
    float4 r;
    r.x = to_tf32(h.x * m.x + p.x * (1.f - m.x));
    r.y = to_tf32(h.y * m.y + p.y * (1.f - m.y));
    r.z = to_tf32(h.z * m.z + p.z * (1.f - m.z));
    r.w = to_tf32(h.w * m.w + p.w * (1.f - m.w));
    return r;
}

__global__ void lnmix3_kernel(const float* __restrict__ x,
                              const float* __restrict__ lw,
                              const float* __restrict__ lb,
                              const float* __restrict__ tmk,
                              const float* __restrict__ tmv,
                              const float* __restrict__ tmr,
                              float* __restrict__ xk,
                              float* __restrict__ xv,
                              float* __restrict__ xr) {
    const int row = blockIdx.x;
    const int tid = threadIdx.x;
    const bool first = (row % TT) == 0;
    const int c4 = tid * 4;

    const float4 cur = *(const float4*)(x + (size_t)row * CC + c4);
    float4 prv = make_float4(0.f, 0.f, 0.f, 0.f);
    if (!first) prv = *(const float4*)(x + (size_t)(row - 1) * CC + c4);

    float muc, invc, mup, invp;
    dual_ln_stats(cur, prv, muc, invc, mup, invp);

    const float4 w4 = *(const float4*)(lw + c4);
    const float4 b4 = *(const float4*)(lb + c4);
    const float4 hc = ln4(cur, muc, invc, w4, b4);
    float4 hp = make_float4(0.f, 0.f, 0.f, 0.f);
    if (!first) hp = ln4(prv, mup, invp, w4, b4);

    const float4 mk = *(const float4*)(tmk + c4);
    const float4 mv = *(const float4*)(tmv + c4);
    const float4 mr = *(const float4*)(tmr + c4);
    const size_t oidx = (size_t)row * CC + c4;
    *(float4*)(xk + oidx) = mixf4(hc, hp, mk);
    *(float4*)(xv + oidx) = mixf4(hc, hp, mv);
    *(float4*)(xr + oidx) = mixf4(hc, hp, mr);
}

__global__ void lnmix2_kernel(const float* __restrict__ x,
                              const float* __restrict__ lw,
                              const float* __restrict__ lb,
                              const float* __restrict__ tmk,
                              const float* __restrict__ tmr,
                              float* __restrict__ xk,
                              float* __restrict__ xr) {
    const int row = blockIdx.x;
    const int tid = threadIdx.x;
    const bool first = (row % TT) == 0;
    const int c4 = tid * 4;

    const float4 cur = *(const float4*)(x + (size_t)row * CC + c4);
    float4 prv = make_float4(0.f, 0.f, 0.f, 0.f);
    if (!first) prv = *(const float4*)(x + (size_t)(row - 1) * CC + c4);

    float muc, invc, mup, invp;
    dual_ln_stats(cur, prv, muc, invc, mup, invp);

    const float4 w4 = *(const float4*)(lw + c4);
    const float4 b4 = *(const float4*)(lb + c4);
    const float4 hc = ln4(cur, muc, invc, w4, b4);
    float4 hp = make_float4(0.f, 0.f, 0.f, 0.f);
    if (!first) hp = ln4(prv, mup, invp, w4, b4);

    const float4 mk = *(const float4*)(tmk + c4);
    const float4 mr = *(const float4*)(tmr + c4);
    const size_t oidx = (size_t)row * CC + c4;
    *(float4*)(xk + oidx) = mixf4(hc, hp, mk);
    *(float4*)(xr + oidx) = mixf4(hc, hp, mr);
}

// ---------------- WKV scan: 4 channels/thread (ILP) + single-exp update ------
// Key identity: with qq = max(pp, ww), one of exp(pp-qq), exp(ww-qq) is
// exactly 1; both collapse to e = __expf(-|pp-ww|) + selects (bit-identical).
#define WKV_PF 4

__device__ __forceinline__ void wkv_step1(float kt, float vt, float srt,
                                          float w, float u,
                                          float& aa, float& bb, float& pp,
                                          float& outv) {
    const float d  = pp - (u + kt);
    const float e  = __expf(-fabsf(d));
    const float e1 = (d >= 0.f) ? 1.f : e;
    const float e2 = (d >= 0.f) ? e : 1.f;
    outv = to_tf32(srt * __fdividef(e1 * aa + e2 * vt, e1 * bb + e2));

    const float ww2 = pp + w;
    const float d2  = ww2 - kt;
    const float eb  = __expf(-fabsf(d2));
    const float e1b = (d2 >= 0.f) ? 1.f : eb;
    const float e2b = (d2 >= 0.f) ? eb : 1.f;
    aa = e1b * aa + e2b * vt;
    bb = e1b * bb + e2b;
    pp = (d2 >= 0.f) ? ww2 : kt;
}

__global__ void wkv_kernel(const float* __restrict__ time_decay,
                           const float* __restrict__ time_first,
                           const float* __restrict__ k,
                           const float* __restrict__ v,
                           const float* __restrict__ sr,
                           float* __restrict__ out) {
    const int gid = blockIdx.x * blockDim.x + threadIdx.x;  // [0, 2048)
    const int b   = gid >> 8;                 // 256 threads per batch
    const int chb = (gid & 255) * 4;          // 4 adjacent channels

    const float4 td = *(const float4*)(time_decay + chb);
    const float4 uu = *(const float4*)(time_first + chb);
    float4 w4;
    w4.x = -__expf(td.x); w4.y = -__expf(td.y);
    w4.z = -__expf(td.z); w4.w = -__expf(td.w);

    const size_t base = (size_t)b * TT * CC + chb;
    const float4* kp = (const float4*)(k  + base);
    const float4* vp = (const float4*)(v  + base);
    const float4* sp = (const float4*)(sr + base);
    float4*       op = (float4*)(out + base);
    const int ld4 = CC / 4;

    // prefetch ring: slot j issued WKV_PF steps ahead of use
    float4 kb[WKV_PF], vb[WKV_PF], sb[WKV_PF];
    #pragma unroll
    for (int j = 0; j < WKV_PF; j++) {
        kb[j] = kp[(size_t)j * ld4];
        vb[j] = vp[(size_t)j * ld4];
        sb[j] = sp[(size_t)j * ld4];
    }

    float4 aa = make_float4(0.f, 0.f, 0.f, 0.f);
    float4 bb = make_float4(0.f, 0.f, 0.f, 0.f);
    float4 pp = make_float4(-1e38f, -1e38f, -1e38f, -1e38f);

    for (int t0 = 0; t0 < TT; t0 += WKV_PF) {
        #pragma unroll
        for (int j = 0; j < WKV_PF; j++) {
            const int t = t0 + j;
            const float4 kt  = kb[j];
            const float4 vt  = vb[j];
            const float4 srt = sb[j];

            const int tn = t + WKV_PF;
            if (tn < TT) {
                kb[j] = kp[(size_t)tn * ld4];
                vb[j] = vp[(size_t)tn * ld4];
                sb[j] = sp[(size_t)tn * ld4];
            }

            float4 o;
            wkv_step1(kt.x, vt.x, srt.x, w4.x, uu.x, aa.x, bb.x, pp.x, o.x);
            wkv_step1(kt.y, vt.y, srt.y, w4.y, uu.y, aa.y, bb.y, pp.y, o.y);
            wkv_step1(kt.z, vt.z, srt.z, w4.z, uu.z, aa.z, bb.z, pp.z, o.z);
            wkv_step1(kt.w, vt.w, srt.w, w4.w, uu.w, aa.w, bb.w, pp.w, o.w);
            op[(size_t)t * ld4] = o;
        }
    }
}

// ---------------- tf32 mma.sync GEMM body ------------------------------------
#define EPI_NONE    0
#define EPI_SIGMOID 1
#define EPI_RELUSQ  2   // output tf32-rounded (feeds next GEMM)
#define EPI_ADDRES  3   // C = aux + acc
#define EPI_FINAL   4   // C = C + aux * acc

#define STG 32768                     // A 16KB + B 16KB per stage
#define SMEM_DYN (3 * STG)            // 3-stage pipeline, 96KB

__device__ __forceinline__ void load_stage(const float* __restrict__ Ab,
                                           const float* __restrict__ Bb,
                                           int K, uint32_t sA, int tid) {
    #pragma unroll
    for (int i = 0; i < 4; i++) {
        const uint32_t u  = tid + i * 256;      // float4 index 0..1023
        const uint32_t r  = u >> 3, c4 = u & 7;
        const uint32_t sa = sA + r * 128 + (c4 ^ (r & 7)) * 16;
        const float* ga = Ab + (size_t)r * K + c4 * 4;
        const float* gb = Bb + (size_t)r * K + c4 * 4;
        asm volatile("cp.async.cg.shared.global [%0], [%1], 16;" :: "r"(sa), "l"(ga));
        asm volatile("cp.async.cg.shared.global [%0], [%1], 16;" :: "r"(sa + 16384), "l"(gb));
    }
}

// Full GEMM body for one 128x128 output tile; epi is a runtime switch.
__device__ __forceinline__ void gemm_body(const float* __restrict__ A,
                                          const float* __restrict__ B,
                                          float* __restrict__ C,
                                          const float* __restrict__ aux,
                                          int K, int M, int brow, int bcol,
                                          int epi, char* smem) {
    const uint32_t sb = s2u(smem);
    const int tid   = threadIdx.x;
    const int lane  = tid & 31, wid = tid >> 5;
    const int warp_m = wid & 1;
    const int warp_n = wid >> 1;
    const int group = lane >> 2, tig = lane & 3;

    const float* Ab = A + (size_t)brow * K;
    const float* Bb = B + (size_t)bcol * K;

    const uint32_t s7  = (uint32_t)(lane & 7);
    const uint32_t hiA = (uint32_t)(lane >> 4);
    const uint32_t hiB = (uint32_t)((lane >> 3) & 1);
    uint32_t rowAoff[4], rowBoff[4];
    #pragma unroll
    for (int mt = 0; mt < 4; mt++)
        rowAoff[mt] = (uint32_t)(warp_m * 64 + mt * 16 + (lane & 15)) * 128u;
    #pragma unroll
    for (int nt = 0; nt < 4; nt++)
        rowBoff[nt] = 16384u + (uint32_t)(warp_n * 32 + nt * 8 + (lane & 7)) * 128u;

    float acc[4][4][4];
    #pragma unroll
    for (int m = 0; m < 4; m++)
        #pragma unroll
        for (int n = 0; n < 4; n++)
            #pragma unroll
            for (int q = 0; q < 4; q++) acc[m][n][q] = 0.f;

    const int NT = K / 32;

    load_stage(Ab,      Bb,      K, sb,       tid);
    asm volatile("cp.async.commit_group;" ::: "memory");
    load_stage(Ab + 32, Bb + 32, K, sb + STG, tid);
    asm volatile("cp.async.commit_group;" ::: "memory");

    for (int kt = 0; kt < NT; kt++) {
        asm volatile("cp.async.wait_group 1;" ::: "memory");
        __syncthreads();

        if (kt + 2 < NT)
            load_stage(Ab + (kt + 2) * 32, Bb + (kt + 2) * 32, K,
                       sb + ((kt + 2) % 3) * STG, tid);
        asm volatile("cp.async.commit_group;" ::: "memory");

        const uint32_t st = sb + (uint32_t)(kt % 3) * STG;

        #pragma unroll
        for (int k8 = 0; k8 < 4; k8++) {
            const uint32_t coffA = (((uint32_t)(2 * k8) + hiA) ^ s7) << 4;
            const uint32_t coffB = (((uint32_t)(2 * k8) + hiB) ^ s7) << 4;
            uint32_t a[4][4], b[4][2];
            #pragma unroll
            for (int mt = 0; mt < 4; mt++)
                ldsm_x4(st + rowAoff[mt] + coffA, a[mt]);
            #pragma unroll
            for (int nt = 0; nt < 4; nt++)
                ldsm_x2(st + rowBoff[nt] + coffB, b[nt]);
            #pragma unroll
            for (int mt = 0; mt < 4; mt++)
                #pragma unroll
                for (int nt = 0; nt < 4; nt++)
                    mma_tf32(acc[mt][nt], a[mt], b[nt]);
        }
    }

    #pragma unroll
    for (int mt = 0; mt < 4; mt++) {
        const int row0 = brow + warp_m * 64 + mt * 16 + group;
        #pragma unroll
        for (int nt = 0; nt < 4; nt++) {
            const int col = bcol + warp_n * 32 + nt * 8 + tig * 2;
            #pragma unroll
            for (int hh = 0; hh < 2; hh++) {
                const size_t idx = (size_t)(row0 + hh * 8) * M + col;
                float v0 = acc[mt][nt][hh * 2 + 0];
                float v1 = acc[mt][nt][hh * 2 + 1];
                float2 o;
                if (epi == EPI_NONE) {
                    o = make_float2(v0, v1);
                } else if (epi == EPI_SIGMOID) {
                    o.x = 1.f / (1.f + __expf(-v0));
                    o.y = 1.f / (1.f + __expf(-v1));
                } else if (epi == EPI_RELUSQ) {
                    float r0 = fmaxf(v0, 0.f), r1 = fmaxf(v1, 0.f);
                    o.x = to_tf32(r0 * r0);
                    o.y = to_tf32(r1 * r1);
                } else if (epi == EPI_ADDRES) {
                    const float2 r = *(const float2*)(aux + idx);
                    o = make_float2(r.x + v0, r.y + v1);
                } else {  // EPI_FINAL
                    const float2 r  = *(const float2*)(aux + idx);
                    const float2 cc = *(const float2*)(C + idx);
                    o.x = cc.x + r.x * v0;
                    o.y = cc.y + r.y * v1;
                }
                *(float2*)(C + idx) = o;
            }
        }
    }
}

// Standalone template kernel (Wo residual, Wval final)
template <int EPI>
__global__ void __launch_bounds__(256, 2)
tgemm_kernel(const float* __restrict__ A,
             const float* __restrict__ B,
             float* __restrict__ C,
             const float* __restrict__ aux,
             int K, int M) {
    extern __shared__ __align__(16) char smem[];
    gemm_body(A, B, C, aux, K, M, blockIdx.y * 128, blockIdx.x * 128, EPI, smem);
}

// Batched k/v/sr GEMMs: grid (8, 128, 3)
__global__ void __launch_bounds__(256, 2)
tgemm_kvr_kernel(const float* __restrict__ xk,
                 const float* __restrict__ xv,
                 const float* __restrict__ xr,
                 const float* __restrict__ w,
                 float* __restrict__ k,
                 float* __restrict__ v,
                 float* __restrict__ sr) {
    extern __shared__ __align__(16) char smem[];
    const int z = blockIdx.z;
    const float* A = (z == 0) ? xk : (z == 1) ? xv : xr;
    const float* B = w + (size_t)z * 1048576;      // WOFF_K/V/R are consecutive
    float* C       = (z == 0) ? k  : (z == 1) ? v  : sr;
    const int epi  = (z == 2) ? EPI_SIGMOID : EPI_NONE;
    gemm_body(A, B, C, nullptr, CC, CC, blockIdx.y * 128, blockIdx.x * 128, epi, smem);
}

// Batched FFN GEMMs: grid (40, 128); x<32 -> Wkey(relusq), else -> Wrec(sigmoid)
__global__ void __launch_bounds__(256, 2)
tgemm_ff_kernel(const float* __restrict__ xk,
                const float* __restrict__ xr,
                const float* __restrict__ w,
                float* __restrict__ kk,
                float* __restrict__ sr) {
    extern __shared__ __align__(16) char smem[];
    const int bx = blockIdx.x;
    if (bx < 32) {
        gemm_body(xk, w + WOFF_KEY, kk, nullptr, CC, FF,
                  blockIdx.y * 128, bx * 128, EPI_RELUSQ, smem);
    } else {
        gemm_body(xr, w + WOFF_REC, sr, nullptr, CC, CC,
                  blockIdx.y * 128, (bx - 32) * 128, EPI_SIGMOID, smem);
    }
}

// ---------------- launch ------------------------------------------------------
extern "C" void kernel_launch(void* const* d_in, const int* in_sizes, int n_in,
                              void* d_out, int out_size) {
    const float* x     = (const float*)d_in[0];
    const float* ln1_w = (const float*)d_in[1];
    const float* ln1_b = (const float*)d_in[2];
    const float* ln2_w = (const float*)d_in[3];
    const float* ln2_b = (const float*)d_in[4];
    const float* atmk  = (const float*)d_in[5];
    const float* atmv  = (const float*)d_in[6];
    const float* atmr  = (const float*)d_in[7];
    const float* tdec  = (const float*)d_in[8];
    const float* tfir  = (const float*)d_in[9];
    const float* Wk    = (const float*)d_in[10];
    const float* Wv    = (const float*)d_in[11];
    const float* Wr    = (const float*)d_in[12];
    const float* Wo    = (const float*)d_in[13];
    const float* ftmk  = (const float*)d_in[14];
    const float* ftmr  = (const float*)d_in[15];
    const float* Wkey  = (const float*)d_in[16];
    const float* Wrec  = (const float*)d_in[17];
    const float* Wval  = (const float*)d_in[18];
    float* out = (float*)d_out;

    float *xk, *xv, *xr, *k, *v, *sr, *kk, *w;
    cudaGetSymbolAddress((void**)&xk, g_xk);
    cudaGetSymbolAddress((void**)&xv, g_xv);
    cudaGetSymbolAddress((void**)&xr, g_xr);
    cudaGetSymbolAddress((void**)&k,  g_k);
    cudaGetSymbolAddress((void**)&v,  g_v);
    cudaGetSymbolAddress((void**)&sr, g_sr);
    cudaGetSymbolAddress((void**)&kk, g_kk);
    cudaGetSymbolAddress((void**)&w,  g_w);

    cudaFuncSetAttribute(tgemm_kernel<EPI_ADDRES>, cudaFuncAttributeMaxDynamicSharedMemorySize, SMEM_DYN);
    cudaFuncSetAttribute(tgemm_kernel<EPI_FINAL>,  cudaFuncAttributeMaxDynamicSharedMemorySize, SMEM_DYN);
    cudaFuncSetAttribute(tgemm_kvr_kernel,         cudaFuncAttributeMaxDynamicSharedMemorySize, SMEM_DYN);
    cudaFuncSetAttribute(tgemm_ff_kernel,          cudaFuncAttributeMaxDynamicSharedMemorySize, SMEM_DYN);

    const dim3 gKVR(8, 128, 3);    // 3072 CTAs: Wk, Wv, Wr batched
    const dim3 gFF(40, 128);       // 5120 CTAs: Wkey (32 cols) + Wrec (8 cols)
    const dim3 gC(8, 128);         // single 1024-CTA GEMMs (Wo, Wval)

    // ---- time-mix (attention) ----
    round_all_kernel<<<13 * 262144 / 256, 256>>>(Wk, Wv, Wr, Wo, Wkey, Wrec, Wval, w);  // 0
    lnmix3_kernel<<<NN, 256>>>(x, ln1_w, ln1_b, atmk, atmv, atmr, xk, xv, xr);           // 1
    tgemm_kvr_kernel<<<gKVR, 256, SMEM_DYN>>>(xk, xv, xr, w, k, v, sr);                  // 2
    wkv_kernel<<<128, 16>>>(tdec, tfir, k, v, sr, xk);   // xk <- tf32(sr*wkv)             3 (ncu slot)
    tgemm_kernel<EPI_ADDRES><<<gC, 256, SMEM_DYN>>>(xk, w + WOFF_O, out, x, CC, CC);     // 4

    // ---- channel-mix (FFN) ----
    lnmix2_kernel<<<NN, 256>>>(out, ln2_w, ln2_b, ftmk, ftmr, xk, xr);                   // 5
    tgemm_ff_kernel<<<gFF, 256, SMEM_DYN>>>(xk, xr, w, kk, sr);                          // 6
    tgemm_kernel<EPI_FINAL><<<gC, 256, SMEM_DYN>>>(kk, w + WOFF_VAL, out, sr, FF, CC);   // 7
}

// round 15
// speedup vs baseline: 1.0879x; 1.0879x over previous
#include <cuda_runtime.h>
#include <math.h>
#include <stdint.h>

#define BB 8
#define TT 2048
#define CC 1024
#define FF 4096
#define NN (BB * TT)   // 16384 rows

// ---------------- scratch (device globals; no allocation allowed) -----------
__device__ float g_xk[NN * CC];
__device__ float g_xv[NN * CC];
__device__ float g_xr[NN * CC];
__device__ float g_k [NN * CC];
__device__ float g_v [NN * CC];
__device__ float g_sr[NN * CC];
__device__ float g_kk[(size_t)NN * FF];
__device__ float g_w [13 * 1024 * 1024];   // tf32-rounded weights

#define WOFF_K   (0 * 1048576)
#define WOFF_V   (1 * 1048576)
#define WOFF_R   (2 * 1048576)
#define WOFF_O   (3 * 1048576)
#define WOFF_KEY (4 * 1048576)
#define WOFF_REC (8 * 1048576)
#define WOFF_VAL (9 * 1048576)

// ---------------- helpers ----------------------------------------------------
__device__ __forceinline__ float to_tf32(float x) {
    uint32_t u;
    asm("cvt.rna.tf32.f32 %0, %1;" : "=r"(u) : "f"(x));
    return __uint_as_float(u);
}

__device__ __forceinline__ uint32_t s2u(const void* p) {
    uint32_t a;
    asm("{ .reg .u64 t; cvta.to.shared.u64 t, %1; cvt.u32.u64 %0, t; }" : "=r"(a) : "l"(p));
    return a;
}

__device__ __forceinline__ void mma_tf32(float* c, const uint32_t* a, const uint32_t* b) {
    asm volatile(
        "mma.sync.aligned.m16n8k8.row.col.f32.tf32.tf32.f32 "
        "{%0,%1,%2,%3}, {%4,%5,%6,%7}, {%8,%9}, {%0,%1,%2,%3};"
        : "+f"(c[0]), "+f"(c[1]), "+f"(c[2]), "+f"(c[3])
        : "r"(a[0]), "r"(a[1]), "r"(a[2]), "r"(a[3]), "r"(b[0]), "r"(b[1]));
}

__device__ __forceinline__ void ldsm_x4(uint32_t addr, uint32_t* r) {
    asm volatile("ldmatrix.sync.aligned.m8n8.x4.shared.b16 {%0,%1,%2,%3}, [%4];"
        : "=r"(r[0]), "=r"(r[1]), "=r"(r[2]), "=r"(r[3]) : "r"(addr));
}

__device__ __forceinline__ void ldsm_x2(uint32_t addr, uint32_t* r) {
    asm volatile("ldmatrix.sync.aligned.m8n8.x2.shared.b16 {%0,%1}, [%2];"
        : "=r"(r[0]), "=r"(r[1]) : "r"(addr));
}

// ---------------- weight tf32 pre-round (single fused kernel) ----------------
__global__ void round_all_kernel(const float* __restrict__ Wk,
                                 const float* __restrict__ Wv,
                                 const float* __restrict__ Wr,
                                 const float* __restrict__ Wo,
                                 const float* __restrict__ Wkey,
                                 const float* __restrict__ Wrec,
                                 const float* __restrict__ Wval,
                                 float* __restrict__ w) {
    const int i = blockIdx.x * blockDim.x + threadIdx.x;   // float4 index
    const int S = 262144;                                   // 1M floats in float4
    const float* src; float* dst; int off;
    if (i < S)            { src = Wk;   dst = w + WOFF_K;   off = i; }
    else if (i < 2 * S)   { src = Wv;   dst = w + WOFF_V;   off = i - S; }
    else if (i < 3 * S)   { src = Wr;   dst = w + WOFF_R;   off = i - 2 * S; }
    else if (i < 4 * S)   { src = Wo;   dst = w + WOFF_O;   off = i - 3 * S; }
    else if (i < 8 * S)   { src = Wkey; dst = w + WOFF_KEY; off = i - 4 * S; }
    else if (i < 9 * S)   { src = Wrec; dst = w + WOFF_REC; off = i - 8 * S; }
    else                  { src = Wval; dst = w + WOFF_VAL; off = i - 9 * S; }
    float4 v = ((const float4*)src)[off];
    v.x = to_tf32(v.x); v.y = to_tf32(v.y);
    v.z = to_tf32(v.z); v.w = to_tf32(v.w);
    ((float4*)dst)[off] = v;
}

// ---------------- fused LayerNorm + token-shift mix ---------------------------
__device__ __forceinline__ void dual_ln_stats(float4 c4, float4 p4,
                                              float& muc, float& invc,
                                              float& mup, float& invp) {
    float sc  = c4.x + c4.y + c4.z + c4.w;
    float sc2 = c4.x * c4.x + c4.y * c4.y + c4.z * c4.z + c4.w * c4.w;
    float sp  = p4.x + p4.y + p4.z + p4.w;
    float sp2 = p4.x * p4.x + p4.y * p4.y + p4.z * p4.z + p4.w * p4.w;

    __shared__ float sh[4][8];
    const int tid = threadIdx.x, wid = tid >> 5, lid = tid & 31;
    #pragma unroll
    for (int o = 16; o > 0; o >>= 1) {
        sc  += __shfl_xor_sync(0xffffffffu, sc,  o);
        sc2 += __shfl_xor_sync(0xffffffffu, sc2, o);
        sp  += __shfl_xor_sync(0xffffffffu, sp,  o);
        sp2 += __shfl_xor_sync(0xffffffffu, sp2, o);
    }
    if (lid == 0) { sh[0][wid] = sc; sh[1][wid] = sc2; sh[2][wid] = sp; sh[3][wid] = sp2; }
    __syncthreads();
    if (wid == 0) {
        float a0 = (lid < 8) ? sh[0][lid] : 0.f;
        float a1 = (lid < 8) ? sh[1][lid] : 0.f;
        float a2 = (lid < 8) ? sh[2][lid] : 0.f;
        float a3 = (lid < 8) ? sh[3][lid] : 0.f;
        #pragma unroll
        for (int o = 4; o > 0; o >>= 1) {
            a0 += __shfl_xor_sync(0xffffffffu, a0, o);
            a1 += __shfl_xor_sync(0xffffffffu, a1, o);
            a2 += __shfl_xor_sync(0xffffffffu, a2, o);
            a3 += __shfl_xor_sync(0xffffffffu, a3, o);
        }
        if (lid == 0) { sh[0][0] = a0; sh[1][0] = a1; sh[2][0] = a2; sh[3][0] = a3; }
    }
    __syncthreads();
    muc = sh[0][0] * (1.0f / CC);
    float varc = fmaxf(sh[1][0] * (1.0f / CC) - muc * muc, 0.f);
    invc = rsqrtf(varc + 1e-5f);
    mup = sh[2][0] * (1.0f / CC);
    float varp = fmaxf(sh[3][0] * (1.0f / CC) - mup * mup, 0.f);
    invp = rsqrtf(varp + 1e-5f);
}

__device__ __forceinline__ float4 ln4(float4 v, float mu, float inv, float4 w, float4 b) {
    float4 r;
    r.x = (v.x - mu) * inv * w.x + b.x;
    r.y = (v.y - mu) * inv * w.y + b.y;
    r.z = (v.z - mu) * inv * w.z + b.z;
    r.w = (v.w - mu) * inv * w.w + b.w;
    return r;
}

__device__ __forceinline__ float4 mixf4(float4 h, float4 p, float4 m) {
    float4 r;
    r.x = to_tf32(h.x * m.x + p.x * (1.f - m.x));
    r.y = to_tf32(h.y * m.y + p.y * (1.f - m.y));
    r.z = to_tf32(h.z * m.z + p.z * (1.f - m.z));
    r.w = to_tf32(h.w * m.w + p.w * (1.f - m.w));
    return r;
}

__global__ void lnmix3_kernel(const float* __restrict__ x,
                              const float* __restrict__ lw,
                              const float* __restrict__ lb,
                              const float* __restrict__ tmk,
                              const float* __restrict__ tmv,
                              const float* __restrict__ tmr,
                              float* __restrict__ xk,
                              float* __restrict__ xv,
                              float* __restrict__ xr) {
    const int row = blockIdx.x;
    const int tid = threadIdx.x;
    const bool first = (row % TT) == 0;
    const int c4 = tid * 4;

    const float4 cur = *(const float4*)(x + (size_t)row * CC + c4);
    float4 prv = make_float4(0.f, 0.f, 0.f, 0.f);
    if (!first) prv = *(const float4*)(x + (size_t)(row - 1) * CC + c4);

    float muc, invc, mup, invp;
    dual_ln_stats(cur, prv, muc, invc, mup, invp);

    const float4 w4 = *(const float4*)(lw + c4);
    const float4 b4 = *(const float4*)(lb + c4);
    const float4 hc = ln4(cur, muc, invc, w4, b4);
    float4 hp = make_float4(0.f, 0.f, 0.f, 0.f);
    if (!first) hp = ln4(prv, mup, invp, w4, b4);

    const float4 mk = *(const float4*)(tmk + c4);
    const float4 mv = *(const float4*)(tmv + c4);
    const float4 mr = *(const float4*)(tmr + c4);
    const size_t oidx = (size_t)row * CC + c4;
    *(float4*)(xk + oidx) = mixf4(hc, hp, mk);
    *(float4*)(xv + oidx) = mixf4(hc, hp, mv);
    *(float4*)(xr + oidx) = mixf4(hc, hp, mr);
}

__global__ void lnmix2_kernel(const float* __restrict__ x,
                              const float* __restrict__ lw,
                              const float* __restrict__ lb,
                              const float* __restrict__ tmk,
                              const float* __restrict__ tmr,
                              float* __restrict__ xk,
                              float* __restrict__ xr) {
    const int row = blockIdx.x;
    const int tid = threadIdx.x;
    const bool first = (row % TT) == 0;
    const int c4 = tid * 4;

    const float4 cur = *(const float4*)(x + (size_t)row * CC + c4);
    float4 prv = make_float4(0.f, 0.f, 0.f, 0.f);
    if (!first) prv = *(const float4*)(x + (size_t)(row - 1) * CC + c4);

    float muc, invc, mup, invp;
    dual_ln_stats(cur, prv, muc, invc, mup, invp);

    const float4 w4 = *(const float4*)(lw + c4);
    const float4 b4 = *(const float4*)(lb + c4);
    const float4 hc = ln4(cur, muc, invc, w4, b4);
    float4 hp = make_float4(0.f, 0.f, 0.f, 0.f);
    if (!first) hp = ln4(prv, mup, invp, w4, b4);

    const float4 mk = *(const float4*)(tmk + c4);
    const float4 mr = *(const float4*)(tmr + c4);
    const size_t oidx = (size_t)row * CC + c4;
    *(float4*)(xk + oidx) = mixf4(hc, hp, mk);
    *(float4*)(xr + oidx) = mixf4(hc, hp, mr);
}

// ---------------- WKV scan: R10 layout (grid128/block64) + single-exp step ---
// Identity: with qq = max(pp, ww), one of exp(pp-qq), exp(ww-qq) is exactly 1;
// both collapse to e = __expf(-|pp-ww|) + selects (bit-identical, exp(0)=1).
#define WKV_PF 8

__global__ void wkv_kernel(const float* __restrict__ time_decay,
                           const float* __restrict__ time_first,
                           const float* __restrict__ k,
                           const float* __restrict__ v,
                           const float* __restrict__ sr,
                           float* __restrict__ out) {
    const int gid = blockIdx.x * blockDim.x + threadIdx.x;  // 64-thread blocks
    const int b  = gid / CC;
    const int ch = gid % CC;
    const float w = -__expf(time_decay[ch]);
    const float u = time_first[ch];

    const size_t base = (size_t)b * TT * CC + ch;
    const float* kp = k  + base;
    const float* vp = v  + base;
    const float* sp = sr + base;
    float*       op = out + base;

    // register prefetch ring: loads issued WKV_PF steps ahead of consumption
    float kb[WKV_PF], vb[WKV_PF], sb[WKV_PF];
    #pragma unroll
    for (int j = 0; j < WKV_PF; j++) {
        kb[j] = kp[(size_t)j * CC];
        vb[j] = vp[(size_t)j * CC];
        sb[j] = sp[(size_t)j * CC];
    }

    float aa = 0.f, bb = 0.f, pp = -1e38f;

    for (int t0 = 0; t0 < TT; t0 += WKV_PF) {
        #pragma unroll
        for (int j = 0; j < WKV_PF; j++) {
            const int t = t0 + j;
            const float kt  = kb[j];
            const float vt  = vb[j];
            const float srt = sb[j];

            const int tn = t + WKV_PF;
            if (tn < TT) {
                kb[j] = kp[(size_t)tn * CC];
                vb[j] = vp[(size_t)tn * CC];
                sb[j] = sp[(size_t)tn * CC];
            }

            // output path (off the carried chain except via aa/bb/pp reads)
            const float d  = pp - (u + kt);
            const float e  = __expf(-fabsf(d));
            const float e1 = (d >= 0.f) ? 1.f : e;
            const float e2 = (d >= 0.f) ? e : 1.f;
            op[(size_t)t * CC] =
                to_tf32(srt * __fdividef(e1 * aa + e2 * vt, e1 * bb + e2));

            // carried-state update
            const float ww2 = pp + w;
            const float d2  = ww2 - kt;
            const float eb  = __expf(-fabsf(d2));
            const float e1b = (d2 >= 0.f) ? 1.f : eb;
            const float e2b = (d2 >= 0.f) ? eb : 1.f;
            aa = e1b * aa + e2b * vt;
            bb = e1b * bb + e2b;
            pp = (d2 >= 0.f) ? ww2 : kt;
        }
    }
}

// ---------------- tf32 mma.sync GEMM body ------------------------------------
#define EPI_NONE    0
#define EPI_SIGMOID 1
#define EPI_RELUSQ  2   // output tf32-rounded (feeds next GEMM)
#define EPI_ADDRES  3   // C = aux + acc
#define EPI_FINAL   4   // C = C + aux * acc

#define STG 32768                     // A 16KB + B 16KB per stage
#define SMEM_DYN (3 * STG)            // 3-stage pipeline, 96KB

__device__ __forceinline__ void load_stage(const float* __restrict__ Ab,
                                           const float* __restrict__ Bb,
                                           int K, uint32_t sA, int tid) {
    #pragma unroll
    for (int i = 0; i < 4; i++) {
        const uint32_t u  = tid + i * 256;      // float4 index 0..1023
        const uint32_t r  = u >> 3, c4 = u & 7;
        const uint32_t sa = sA + r * 128 + (c4 ^ (r & 7)) * 16;
        const float* ga = Ab + (size_t)r * K + c4 * 4;
        const float* gb = Bb + (size_t)r * K + c4 * 4;
        asm volatile("cp.async.cg.shared.global [%0], [%1], 16;" :: "r"(sa), "l"(ga));
        asm volatile("cp.async.cg.shared.global [%0], [%1], 16;" :: "r"(sa + 16384), "l"(gb));
    }
}

// Full GEMM body for one 128x128 output tile; epi is a runtime switch.
__device__ __forceinline__ void gemm_body(const float* __restrict__ A,
                                          const float* __restrict__ B,
                                          float* __restrict__ C,
                                          const float* __restrict__ aux,
                                          int K, int M, int brow, int bcol,
                                          int epi, char* smem) {
    const uint32_t sb = s2u(smem);
    const int tid   = threadIdx.x;
    const int lane  = tid & 31, wid = tid >> 5;
    const int warp_m = wid & 1;
    const int warp_n = wid >> 1;
    const int group = lane >> 2, tig = lane & 3;

    const float* Ab = A + (size_t)brow * K;
    const float* Bb = B + (size_t)bcol * K;

    const uint32_t s7  = (uint32_t)(lane & 7);
    const uint32_t hiA = (uint32_t)(lane >> 4);
    const uint32_t hiB = (uint32_t)((lane >> 3) & 1);
    uint32_t rowAoff[4], rowBoff[4];
    #pragma unroll
    for (int mt = 0; mt < 4; mt++)
        rowAoff[mt] = (uint32_t)(warp_m * 64 + mt * 16 + (lane & 15)) * 128u;
    #pragma unroll
    for (int nt = 0; nt < 4; nt++)
        rowBoff[nt] = 16384u + (uint32_t)(warp_n * 32 + nt * 8 + (lane & 7)) * 128u;

    float acc[4][4][4];
    #pragma unroll
    for (int m = 0; m < 4; m++)
        #pragma unroll
        for (int n = 0; n < 4; n++)
            #pragma unroll
            for (int q = 0; q < 4; q++) acc[m][n][q] = 0.f;

    const int NT = K / 32;

    load_stage(Ab,      Bb,      K, sb,       tid);
    asm volatile("cp.async.commit_group;" ::: "memory");
    load_stage(Ab + 32, Bb + 32, K, sb + STG, tid);
    asm volatile("cp.async.commit_group;" ::: "memory");

    for (int kt = 0; kt < NT; kt++) {
        asm volatile("cp.async.wait_group 1;" ::: "memory");
        __syncthreads();

        if (kt + 2 < NT)
            load_stage(Ab + (kt + 2) * 32, Bb + (kt + 2) * 32, K,
                       sb + ((kt + 2) % 3) * STG, tid);
        asm volatile("cp.async.commit_group;" ::: "memory");

        const uint32_t st = sb + (uint32_t)(kt % 3) * STG;

        #pragma unroll
        for (int k8 = 0; k8 < 4; k8++) {
            const uint32_t coffA = (((uint32_t)(2 * k8) + hiA) ^ s7) << 4;
            const uint32_t coffB = (((uint32_t)(2 * k8) + hiB) ^ s7) << 4;
            uint32_t a[4][4], b[4][2];
            #pragma unroll
            for (int mt = 0; mt < 4; mt++)
                ldsm_x4(st + rowAoff[mt] + coffA, a[mt]);
            #pragma unroll
            for (int nt = 0; nt < 4; nt++)
                ldsm_x2(st + rowBoff[nt] + coffB, b[nt]);
            #pragma unroll
            for (int mt = 0; mt < 4; mt++)
                #pragma unroll
                for (int nt = 0; nt < 4; nt++)
                    mma_tf32(acc[mt][nt], a[mt], b[nt]);
        }
    }

    #pragma unroll
    for (int mt = 0; mt < 4; mt++) {
        const int row0 = brow + warp_m * 64 + mt * 16 + group;
        #pragma unroll
        for (int nt = 0; nt < 4; nt++) {
            const int col = bcol + warp_n * 32 + nt * 8 + tig * 2;
            #pragma unroll
            for (int hh = 0; hh < 2; hh++) {
                const size_t idx = (size_t)(row0 + hh * 8) * M + col;
                float v0 = acc[mt][nt][hh * 2 + 0];
                float v1 = acc[mt][nt][hh * 2 + 1];
                float2 o;
                if (epi == EPI_NONE) {
                    o = make_float2(v0, v1);
                } else if (epi == EPI_SIGMOID) {
                    o.x = 1.f / (1.f + __expf(-v0));
                    o.y = 1.f / (1.f + __expf(-v1));
                } else if (epi == EPI_RELUSQ) {
                    float r0 = fmaxf(v0, 0.f), r1 = fmaxf(v1, 0.f);
                    o.x = to_tf32(r0 * r0);
                    o.y = to_tf32(r1 * r1);
                } else if (epi == EPI_ADDRES) {
                    const float2 r = *(const float2*)(aux + idx);
                    o = make_float2(r.x + v0, r.y + v1);
                } else {  // EPI_FINAL
                    const float2 r  = *(const float2*)(aux + idx);
                    const float2 cc = *(const float2*)(C + idx);
                    o.x = cc.x + r.x * v0;
                    o.y = cc.y + r.y * v1;
                }
                *(float2*)(C + idx) = o;
            }
        }
    }
}

// Standalone template kernel (Wo residual, Wval final)
template <int EPI>
__global__ void __launch_bounds__(256, 2)
tgemm_kernel(const float* __restrict__ A,
             const float* __restrict__ B,
             float* __restrict__ C,
             const float* __restrict__ aux,
             int K, int M) {
    extern __shared__ __align__(16) char smem[];
    gemm_body(A, B, C, aux, K, M, blockIdx.y * 128, blockIdx.x * 128, EPI, smem);
}

// Batched k/v/sr GEMMs: grid (8, 128, 3)
__global__ void __launch_bounds__(256, 2)
tgemm_kvr_kernel(const float* __restrict__ xk,
                 const float* __restrict__ xv,
                 const float* __restrict__ xr,
                 const float* __restrict__ w,
                 float* __restrict__ k,
                 float* __restrict__ v,
                 float* __restrict__ sr) {
    extern __shared__ __align__(16) char smem[];
    const int z = blockIdx.z;
    const float* A = (z == 0) ? xk : (z == 1) ? xv : xr;
    const float* B = w + (size_t)z * 1048576;      // WOFF_K/V/R are consecutive
    float* C       = (z == 0) ? k  : (z == 1) ? v  : sr;
    const int epi  = (z == 2) ? EPI_SIGMOID : EPI_NONE;
    gemm_body(A, B, C, nullptr, CC, CC, blockIdx.y * 128, blockIdx.x * 128, epi, smem);
}

// Batched FFN GEMMs: grid (40, 128); x<32 -> Wkey(relusq), else -> Wrec(sigmoid)
__global__ void __launch_bounds__(256, 2)
tgemm_ff_kernel(const float* __restrict__ xk,
                const float* __restrict__ xr,
                const float* __restrict__ w,
                float* __restrict__ kk,
                float* __restrict__ sr) {
    extern __shared__ __align__(16) char smem[];
    const int bx = blockIdx.x;
    if (bx < 32) {
        gemm_body(xk, w + WOFF_KEY, kk, nullptr, CC, FF,
                  blockIdx.y * 128, bx * 128, EPI_RELUSQ, smem);
    } else {
        gemm_body(xr, w + WOFF_REC, sr, nullptr, CC, CC,
                  blockIdx.y * 128, (bx - 32) * 128, EPI_SIGMOID, smem);
    }
}

// ---------------- launch ------------------------------------------------------
extern "C" void kernel_launch(void* const* d_in, const int* in_sizes, int n_in,
                              void* d_out, int out_size) {
    const float* x     = (const float*)d_in[0];
    const float* ln1_w = (const float*)d_in[1];
    const float* ln1_b = (const float*)d_in[2];
    const float* ln2_w = (const float*)d_in[3];
    const float* ln2_b = (const float*)d_in[4];
    const float* atmk  = (const float*)d_in[5];
    const float* atmv  = (const float*)d_in[6];
    const float* atmr  = (const float*)d_in[7];
    const float* tdec  = (const float*)d_in[8];
    const float* tfir  = (const float*)d_in[9];
    const float* Wk    = (const float*)d_in[10];
    const float* Wv    = (const float*)d_in[11];
    const float* Wr    = (const float*)d_in[12];
    const float* Wo    = (const float*)d_in[13];
    const float* ftmk  = (const float*)d_in[14];
    const float* ftmr  = (const float*)d_in[15];
    const float* Wkey  = (const float*)d_in[16];
    const float* Wrec  = (const float*)d_in[17];
    const float* Wval  = (const float*)d_in[18];
    float* out = (float*)d_out;

    float *xk, *xv, *xr, *k, *v, *sr, *kk, *w;
    cudaGetSymbolAddress((void**)&xk, g_xk);
    cudaGetSymbolAddress((void**)&xv, g_xv);
    cudaGetSymbolAddress((void**)&xr, g_xr);
    cudaGetSymbolAddress((void**)&k,  g_k);
    cudaGetSymbolAddress((void**)&v,  g_v);
    cudaGetSymbolAddress((void**)&sr, g_sr);
    cudaGetSymbolAddress((void**)&kk, g_kk);
    cudaGetSymbolAddress((void**)&w,  g_w);

    cudaFuncSetAttribute(tgemm_kernel<EPI_ADDRES>, cudaFuncAttributeMaxDynamicSharedMemorySize, SMEM_DYN);
    cudaFuncSetAttribute(tgemm_kernel<EPI_FINAL>,  cudaFuncAttributeMaxDynamicSharedMemorySize, SMEM_DYN);
    cudaFuncSetAttribute(tgemm_kvr_kernel,         cudaFuncAttributeMaxDynamicSharedMemorySize, SMEM_DYN);
    cudaFuncSetAttribute(tgemm_ff_kernel,          cudaFuncAttributeMaxDynamicSharedMemorySize, SMEM_DYN);

    const dim3 gKVR(8, 128, 3);    // 3072 CTAs: Wk, Wv, Wr batched
    const dim3 gFF(40, 128);       // 5120 CTAs: Wkey (32 cols) + Wrec (8 cols)
    const dim3 gC(8, 128);         // single 1024-CTA GEMMs (Wo, Wval)

    // ---- time-mix (attention) ----
    round_all_kernel<<<13 * 262144 / 256, 256>>>(Wk, Wv, Wr, Wo, Wkey, Wrec, Wval, w);  // 0
    lnmix3_kernel<<<NN, 256>>>(x, ln1_w, ln1_b, atmk, atmv, atmr, xk, xv, xr);           // 1
    tgemm_kvr_kernel<<<gKVR, 256, SMEM_DYN>>>(xk, xv, xr, w, k, v, sr);                  // 2
    wkv_kernel<<<BB * CC / 64, 64>>>(tdec, tfir, k, v, sr, xk);  // xk <- tf32(sr*wkv)    3 (ncu slot)
    tgemm_kernel<EPI_ADDRES><<<gC, 256, SMEM_DYN>>>(xk, w + WOFF_O, out, x, CC, CC);     // 4

    // ---- channel-mix (FFN) ----
    lnmix2_kernel<<<NN, 256>>>(out, ln2_w, ln2_b, ftmk, ftmr, xk, xr);                   // 5
    tgemm_ff_kernel<<<gFF, 256, SMEM_DYN>>>(xk, xr, w, kk, sr);                          // 6
    tgemm_kernel<EPI_FINAL><<<gC, 256, SMEM_DYN>>>(kk, w + WOFF_VAL, out, sr, FF, CC);   // 7
}

// round 17
// speedup vs baseline: 1.1011x; 1.0121x over previous
#include <cuda_runtime.h>
#include <math.h>
#include <stdint.h>

#define BB 8
#define TT 2048
#define CC 1024
#define FF 4096
#define NN (BB * TT)   // 16384 rows

// ---------------- scratch (device globals; no allocation allowed) -----------
__device__ float g_xk[NN * CC];
__device__ float g_xv[NN * CC];
__device__ float g_xr[NN * CC];
__device__ float g_k [NN * CC];
__device__ float g_v [NN * CC];
__device__ float g_sr[NN * CC];
__device__ float g_kk[(size_t)NN * FF];
__device__ float g_w [13 * 1024 * 1024];   // tf32-rounded weights

#define WOFF_K   (0 * 1048576)
#define WOFF_V   (1 * 1048576)
#define WOFF_R   (2 * 1048576)
#define WOFF_O   (3 * 1048576)
#define WOFF_KEY (4 * 1048576)
#define WOFF_REC (8 * 1048576)
#define WOFF_VAL (9 * 1048576)

// ---------------- helpers ----------------------------------------------------
__device__ __forceinline__ float to_tf32(float x) {
    uint32_t u;
    asm("cvt.rna.tf32.f32 %0, %1;" : "=r"(u) : "f"(x));
    return __uint_as_float(u);
}

__device__ __forceinline__ uint32_t s2u(const void* p) {
    uint32_t a;
    asm("{ .reg .u64 t; cvta.to.shared.u64 t, %1; cvt.u32.u64 %0, t; }" : "=r"(a) : "l"(p));
    return a;
}

__device__ __forceinline__ void mma_tf32(float* c, const uint32_t* a, const uint32_t* b) {
    asm volatile(
        "mma.sync.aligned.m16n8k8.row.col.f32.tf32.tf32.f32 "
        "{%0,%1,%2,%3}, {%4,%5,%6,%7}, {%8,%9}, {%0,%1,%2,%3};"
        : "+f"(c[0]), "+f"(c[1]), "+f"(c[2]), "+f"(c[3])
        : "r"(a[0]), "r"(a[1]), "r"(a[2]), "r"(a[3]), "r"(b[0]), "r"(b[1]));
}

__device__ __forceinline__ void ldsm_x4(uint32_t addr, uint32_t* r) {
    asm volatile("ldmatrix.sync.aligned.m8n8.x4.shared.b16 {%0,%1,%2,%3}, [%4];"
        : "=r"(r[0]), "=r"(r[1]), "=r"(r[2]), "=r"(r[3]) : "r"(addr));
}

__device__ __forceinline__ void ldsm_x2(uint32_t addr, uint32_t* r) {
    asm volatile("ldmatrix.sync.aligned.m8n8.x2.shared.b16 {%0,%1}, [%2];"
        : "=r"(r[0]), "=r"(r[1]) : "r"(addr));
}

// ---------------- weight tf32 pre-round (single fused kernel) ----------------
__global__ void round_all_kernel(const float* __restrict__ Wk,
                                 const float* __restrict__ Wv,
                                 const float* __restrict__ Wr,
                                 const float* __restrict__ Wo,
                                 const float* __restrict__ Wkey,
                                 const float* __restrict__ Wrec,
                                 const float* __restrict__ Wval,
                                 float* __restrict__ w) {
    const int i = blockIdx.x * blockDim.x + threadIdx.x;   // float4 index
    const int S = 262144;                                   // 1M floats in float4
    const float* src; float* dst; int off;
    if (i < S)            { src = Wk;   dst = w + WOFF_K;   off = i; }
    else if (i < 2 * S)   { src = Wv;   dst = w + WOFF_V;   off = i - S; }
    else if (i < 3 * S)   { src = Wr;   dst = w + WOFF_R;   off = i - 2 * S; }
    else if (i < 4 * S)   { src = Wo;   dst = w + WOFF_O;   off = i - 3 * S; }
    else if (i < 8 * S)   { src = Wkey; dst = w + WOFF_KEY; off = i - 4 * S; }
    else if (i < 9 * S)   { src = Wrec; dst = w + WOFF_REC; off = i - 8 * S; }
    else                  { src = Wval; dst = w + WOFF_VAL; off = i - 9 * S; }
    float4 v = ((const float4*)src)[off];
    v.x = to_tf32(v.x); v.y = to_tf32(v.y);
    v.z = to_tf32(v.z); v.w = to_tf32(v.w);
    ((float4*)dst)[off] = v;
}

// ---------------- fused LayerNorm + token-shift mix ---------------------------
__device__ __forceinline__ void dual_ln_stats(float4 c4, float4 p4,
                                              float& muc, float& invc,
                                              float& mup, float& invp) {
    float sc  = c4.x + c4.y + c4.z + c4.w;
    float sc2 = c4.x * c4.x + c4.y * c4.y + c4.z * c4.z + c4.w * c4.w;
    float sp  = p4.x + p4.y + p4.z + p4.w;
    float sp2 = p4.x * p4.x + p4.y * p4.y + p4.z * p4.z + p4.w * p4.w;

    __shared__ float sh[4][8];
    const int tid = threadIdx.x, wid = tid >> 5, lid = tid & 31;
    #pragma unroll
    for (int o = 16; o > 0; o >>= 1) {
        sc  += __shfl_xor_sync(0xffffffffu, sc,  o);
        sc2 += __shfl_xor_sync(0xffffffffu, sc2, o);
        sp  += __shfl_xor_sync(0xffffffffu, sp,  o);
        sp2 += __shfl_xor_sync(0xffffffffu, sp2, o);
    }
    if (lid == 0) { sh[0][wid] = sc; sh[1][wid] = sc2; sh[2][wid] = sp; sh[3][wid] = sp2; }
    __syncthreads();
    if (wid == 0) {
        float a0 = (lid < 8) ? sh[0][lid] : 0.f;
        float a1 = (lid < 8) ? sh[1][lid] : 0.f;
        float a2 = (lid < 8) ? sh[2][lid] : 0.f;
        float a3 = (lid < 8) ? sh[3][lid] : 0.f;
        #pragma unroll
        for (int o = 4; o > 0; o >>= 1) {
            a0 += __shfl_xor_sync(0xffffffffu, a0, o);
            a1 += __shfl_xor_sync(0xffffffffu, a1, o);
            a2 += __shfl_xor_sync(0xffffffffu, a2, o);
            a3 += __shfl_xor_sync(0xffffffffu, a3, o);
        }
        if (lid == 0) { sh[0][0] = a0; sh[1][0] = a1; sh[2][0] = a2; sh[3][0] = a3; }
    }
    __syncthreads();
    muc = sh[0][0] * (1.0f / CC);
    float varc = fmaxf(sh[1][0] * (1.0f / CC) - muc * muc, 0.f);
    invc = rsqrtf(varc + 1e-5f);
    mup = sh[2][0] * (1.0f / CC);
    float varp = fmaxf(sh[3][0] * (1.0f / CC) - mup * mup, 0.f);
    invp = rsqrtf(varp + 1e-5f);
}

__device__ __forceinline__ float4 ln4(float4 v, float mu, float inv, float4 w, float4 b) {
    float4 r;
    r.x = (v.x - mu) * inv * w.x + b.x;
    r.y = (v.y - mu) * inv * w.y + b.y;
    r.z = (v.z - mu) * inv * w.z + b.z;
    r.w = (v.w - mu) * inv * w.w + b.w;
    return r;
}

__device__ __forceinline__ float4 mixf4(float4 h, float4 p, float4 m) {
    float4 r;
    r.x = to_tf32(h.x * m.x + p.x * (1.f - m.x));
    r.y = to_tf32(h.y * m.y + p.y * (1.f - m.y));
    r.z = to_tf32(h.z * m.z + p.z * (1.f - m.z));
    r.w = to_tf32(h.w * m.w + p.w * (1.f - m.w));
    return r;
}

__global__ void lnmix3_kernel(const float* __restrict__ x,
                              const float* __restrict__ lw,
                              const float* __restrict__ lb,
                              const float* __restrict__ tmk,
                              const float* __restrict__ tmv,
                              const float* __restrict__ tmr,
                              float* __restrict__ xk,
                              float* __restrict__ xv,
                              float* __restrict__ xr) {
    const int row = blockIdx.x;
    const int tid = threadIdx.x;
    const bool first = (row % TT) == 0;
    const int c4 = tid * 4;

    const float4 cur = *(const float4*)(x + (size_t)row * CC + c4);
    float4 prv = make_float4(0.f, 0.f, 0.f, 0.f);
    if (!first) prv = *(const float4*)(x + (size_t)(row - 1) * CC + c4);

    float muc, invc, mup, invp;
    dual_ln_stats(cur, prv, muc, invc, mup, invp);

    const float4 w4 = *(const float4*)(lw + c4);
    const float4 b4 = *(const float4*)(lb + c4);
    const float4 hc = ln4(cur, muc, invc, w4, b4);
    float4 hp = make_float4(0.f, 0.f, 0.f, 0.f);
    if (!first) hp = ln4(prv, mup, invp, w4, b4);

    const float4 mk = *(const float4*)(tmk + c4);
    const float4 mv = *(const float4*)(tmv + c4);
    const float4 mr = *(const float4*)(tmr + c4);
    const size_t oidx = (size_t)row * CC + c4;
    *(float4*)(xk + oidx) = mixf4(hc, hp, mk);
    *(float4*)(xv + oidx) = mixf4(hc, hp, mv);
    *(float4*)(xr + oidx) = mixf4(hc, hp, mr);
}

__global__ void lnmix2_kernel(const float* __restrict__ x,
                              const float* __restrict__ lw,
                              const float* __restrict__ lb,
                              const float* __restrict__ tmk,
                              const float* __restrict__ tmr,
                              float* __restrict__ xk,
                              float* __restrict__ xr) {
    const int row = blockIdx.x;
    const int tid = threadIdx.x;
    const bool first = (row % TT) == 0;
    const int c4 = tid * 4;

    const float4 cur = *(const float4*)(x + (size_t)row * CC + c4);
    float4 prv = make_float4(0.f, 0.f, 0.f, 0.f);
    if (!first) prv = *(const float4*)(x + (size_t)(row - 1) * CC + c4);

    float muc, invc, mup, invp;
    dual_ln_stats(cur, prv, muc, invc, mup, invp);

    const float4 w4 = *(const float4*)(lw + c4);
    const float4 b4 = *(const float4*)(lb + c4);
    const float4 hc = ln4(cur, muc, invc, w4, b4);
    float4 hp = make_float4(0.f, 0.f, 0.f, 0.f);
    if (!first) hp = ln4(prv, mup, invp, w4, b4);

    const float4 mk = *(const float4*)(tmk + c4);
    const float4 mr = *(const float4*)(tmr + c4);
    const size_t oidx = (size_t)row * CC + c4;
    *(float4*)(xk + oidx) = mixf4(hc, hp, mk);
    *(float4*)(xr + oidx) = mixf4(hc, hp, mr);
}

// ---------------- WKV scan: batched waits (consume-all / load-all / compute) -
// The per-step interleaved prefetch re-armed shared scoreboard slots each step,
// exposing ~full L2 latency per step. Restructure: one wait region per outer
// iteration (copy ring->locals), then issue ALL next-iter loads, then compute
// 8 steps on locals. Loads are consumed a full iteration (~8*60 cyc) later.
#define WKV_PF 8

__global__ void wkv_kernel(const float* __restrict__ time_decay,
                           const float* __restrict__ time_first,
                           const float* __restrict__ k,
                           const float* __restrict__ v,
                           const float* __restrict__ sr,
                           float* __restrict__ out) {
    const int gid = blockIdx.x * blockDim.x + threadIdx.x;  // 64-thread blocks
    const int b  = gid / CC;
    const int ch = gid % CC;
    const float w = -__expf(time_decay[ch]);
    const float u = time_first[ch];

    const size_t base = (size_t)b * TT * CC + ch;
    const float* kp = k  + base;
    const float* vp = v  + base;
    const float* sp = sr + base;
    float*       op = out + base;

    // ring holds data for the CURRENT outer iteration at entry
    float kb[WKV_PF], vb[WKV_PF], sb[WKV_PF];
    #pragma unroll
    for (int j = 0; j < WKV_PF; j++) {
        kb[j] = kp[(size_t)j * CC];
        vb[j] = vp[(size_t)j * CC];
        sb[j] = sp[(size_t)j * CC];
    }

    float aa = 0.f, bb = 0.f, pp = -1e38f;

    for (int t0 = 0; t0 < TT; t0 += WKV_PF) {
        // 1) consume: single wait region (loads here are one full iter old)
        float kc[WKV_PF], vc[WKV_PF], sc[WKV_PF];
        #pragma unroll
        for (int j = 0; j < WKV_PF; j++) {
            kc[j] = kb[j]; vc[j] = vb[j]; sc[j] = sb[j];
        }

        // 2) prefetch next iteration (no consumer until next outer iter)
        const int tn0 = t0 + WKV_PF;
        if (tn0 < TT) {
            #pragma unroll
            for (int j = 0; j < WKV_PF; j++) {
                kb[j] = kp[(size_t)(tn0 + j) * CC];
                vb[j] = vp[(size_t)(tn0 + j) * CC];
                sb[j] = sp[(size_t)(tn0 + j) * CC];
            }
        }

        // 3) compute 8 steps on locals
        #pragma unroll
        for (int j = 0; j < WKV_PF; j++) {
            const int t = t0 + j;
            const float kt  = kc[j];
            const float vt  = vc[j];
            const float srt = sc[j];

            // output path
            const float d  = pp - (u + kt);
            const float e  = __expf(-fabsf(d));
            const float e1 = (d >= 0.f) ? 1.f : e;
            const float e2 = (d >= 0.f) ? e : 1.f;
            op[(size_t)t * CC] =
                to_tf32(srt * __fdividef(e1 * aa + e2 * vt, e1 * bb + e2));

            // carried-state update
            const float ww2 = pp + w;
            const float d2  = ww2 - kt;
            const float eb  = __expf(-fabsf(d2));
            const float e1b = (d2 >= 0.f) ? 1.f : eb;
            const float e2b = (d2 >= 0.f) ? eb : 1.f;
            aa = e1b * aa + e2b * vt;
            bb = e1b * bb + e2b;
            pp = (d2 >= 0.f) ? ww2 : kt;
        }
    }
}

// ---------------- tf32 mma.sync GEMM body ------------------------------------
#define EPI_NONE    0
#define EPI_SIGMOID 1
#define EPI_RELUSQ  2   // output tf32-rounded (feeds next GEMM)
#define EPI_ADDRES  3   // C = aux + acc
#define EPI_FINAL   4   // C = C + aux * acc

#define STG 32768                     // A 16KB + B 16KB per stage
#define SMEM_DYN (3 * STG)            // 3-stage pipeline, 96KB

__device__ __forceinline__ void load_stage(const float* __restrict__ Ab,
                                           const float* __restrict__ Bb,
                                           int K, uint32_t sA, int tid) {
    #pragma unroll
    for (int i = 0; i < 4; i++) {
        const uint32_t u  = tid + i * 256;      // float4 index 0..1023
        const uint32_t r  = u >> 3, c4 = u & 7;
        const uint32_t sa = sA + r * 128 + (c4 ^ (r & 7)) * 16;
        const float* ga = Ab + (size_t)r * K + c4 * 4;
        const float* gb = Bb + (size_t)r * K + c4 * 4;
        asm volatile("cp.async.cg.shared.global [%0], [%1], 16;" :: "r"(sa), "l"(ga));
        asm volatile("cp.async.cg.shared.global [%0], [%1], 16;" :: "r"(sa + 16384), "l"(gb));
    }
}

// Full GEMM body for one 128x128 output tile; epi is a runtime switch.
__device__ __forceinline__ void gemm_body(const float* __restrict__ A,
                                          const float* __restrict__ B,
                                          float* __restrict__ C,
                                          const float* __restrict__ aux,
                                          int K, int M, int brow, int bcol,
                                          int epi, char* smem) {
    const uint32_t sb = s2u(smem);
    const int tid   = threadIdx.x;
    const int lane  = tid & 31, wid = tid >> 5;
    const int warp_m = wid & 1;
    const int warp_n = wid >> 1;
    const int group = lane >> 2, tig = lane & 3;

    const float* Ab = A + (size_t)brow * K;
    const float* Bb = B + (size_t)bcol * K;

    const uint32_t s7  = (uint32_t)(lane & 7);
    const uint32_t hiA = (uint32_t)(lane >> 4);
    const uint32_t hiB = (uint32_t)((lane >> 3) & 1);
    uint32_t rowAoff[4], rowBoff[4];
    #pragma unroll
    for (int mt = 0; mt < 4; mt++)
        rowAoff[mt] = (uint32_t)(warp_m * 64 + mt * 16 + (lane & 15)) * 128u;
    #pragma unroll
    for (int nt = 0; nt < 4; nt++)
        rowBoff[nt] = 16384u + (uint32_t)(warp_n * 32 + nt * 8 + (lane & 7)) * 128u;

    float acc[4][4][4];
    #pragma unroll
    for (int m = 0; m < 4; m++)
        #pragma unroll
        for (int n = 0; n < 4; n++)
            #pragma unroll
            for (int q = 0; q < 4; q++) acc[m][n][q] = 0.f;

    const int NT = K / 32;

    load_stage(Ab,      Bb,      K, sb,       tid);
    asm volatile("cp.async.commit_group;" ::: "memory");
    load_stage(Ab + 32, Bb + 32, K, sb + STG, tid);
    asm volatile("cp.async.commit_group;" ::: "memory");

    for (int kt = 0; kt < NT; kt++) {
        asm volatile("cp.async.wait_group 1;" ::: "memory");
        __syncthreads();

        if (kt + 2 < NT)
            load_stage(Ab + (kt + 2) * 32, Bb + (kt + 2) * 32, K,
                       sb + ((kt + 2) % 3) * STG, tid);
        asm volatile("cp.async.commit_group;" ::: "memory");

        const uint32_t st = sb + (uint32_t)(kt % 3) * STG;

        #pragma unroll
        for (int k8 = 0; k8 < 4; k8++) {
            const uint32_t coffA = (((uint32_t)(2 * k8) + hiA) ^ s7) << 4;
            const uint32_t coffB = (((uint32_t)(2 * k8) + hiB) ^ s7) << 4;
            uint32_t a[4][4], b[4][2];
            #pragma unroll
            for (int mt = 0; mt < 4; mt++)
                ldsm_x4(st + rowAoff[mt] + coffA, a[mt]);
            #pragma unroll
            for (int nt = 0; nt < 4; nt++)
                ldsm_x2(st + rowBoff[nt] + coffB, b[nt]);
            #pragma unroll
            for (int mt = 0; mt < 4; mt++)
                #pragma unroll
                for (int nt = 0; nt < 4; nt++)
                    mma_tf32(acc[mt][nt], a[mt], b[nt]);
        }
    }

    #pragma unroll
    for (int mt = 0; mt < 4; mt++) {
        const int row0 = brow + warp_m * 64 + mt * 16 + group;
        #pragma unroll
        for (int nt = 0; nt < 4; nt++) {
            const int col = bcol + warp_n * 32 + nt * 8 + tig * 2;
            #pragma unroll
            for (int hh = 0; hh < 2; hh++) {
                const size_t idx = (size_t)(row0 + hh * 8) * M + col;
                float v0 = acc[mt][nt][hh * 2 + 0];
                float v1 = acc[mt][nt][hh * 2 + 1];
                float2 o;
                if (epi == EPI_NONE) {
                    o = make_float2(v0, v1);
                } else if (epi == EPI_SIGMOID) {
                    o.x = 1.f / (1.f + __expf(-v0));
                    o.y = 1.f / (1.f + __expf(-v1));
                } else if (epi == EPI_RELUSQ) {
                    float r0 = fmaxf(v0, 0.f), r1 = fmaxf(v1, 0.f);
                    o.x = to_tf32(r0 * r0);
                    o.y = to_tf32(r1 * r1);
                } else if (epi == EPI_ADDRES) {
                    const float2 r = *(const float2*)(aux + idx);
                    o = make_float2(r.x + v0, r.y + v1);
                } else {  // EPI_FINAL
                    const float2 r  = *(const float2*)(aux + idx);
                    const float2 cc = *(const float2*)(C + idx);
                    o.x = cc.x + r.x * v0;
                    o.y = cc.y + r.y * v1;
                }
                *(float2*)(C + idx) = o;
            }
        }
    }
}

// Standalone template kernel (Wo residual, Wval final)
template <int EPI>
__global__ void __launch_bounds__(256, 2)
tgemm_kernel(const float* __restrict__ A,
             const float* __restrict__ B,
             float* __restrict__ C,
             const float* __restrict__ aux,
             int K, int M) {
    extern __shared__ __align__(16) char smem[];
    gemm_body(A, B, C, aux, K, M, blockIdx.y * 128, blockIdx.x * 128, EPI, smem);
}

// Batched k/v/sr GEMMs: grid (8, 128, 3)
__global__ void __launch_bounds__(256, 2)
tgemm_kvr_kernel(const float* __restrict__ xk,
                 const float* __restrict__ xv,
                 const float* __restrict__ xr,
                 const float* __restrict__ w,
                 float* __restrict__ k,
                 float* __restrict__ v,
                 float* __restrict__ sr) {
    extern __shared__ __align__(16) char smem[];
    const int z = blockIdx.z;
    const float* A = (z == 0) ? xk : (z == 1) ? xv : xr;
    const float* B = w + (size_t)z * 1048576;      // WOFF_K/V/R are consecutive
    float* C       = (z == 0) ? k  : (z == 1) ? v  : sr;
    const int epi  = (z == 2) ? EPI_SIGMOID : EPI_NONE;
    gemm_body(A, B, C, nullptr, CC, CC, blockIdx.y * 128, blockIdx.x * 128, epi, smem);
}

// Batched FFN GEMMs: grid (40, 128); x<32 -> Wkey(relusq), else -> Wrec(sigmoid)
__global__ void __launch_bounds__(256, 2)
tgemm_ff_kernel(const float* __restrict__ xk,
                const float* __restrict__ xr,
                const float* __restrict__ w,
                float* __restrict__ kk,
                float* __restrict__ sr) {
    extern __shared__ __align__(16) char smem[];
    const int bx = blockIdx.x;
    if (bx < 32) {
        gemm_body(xk, w + WOFF_KEY, kk, nullptr, CC, FF,
                  blockIdx.y * 128, bx * 128, EPI_RELUSQ, smem);
    } else {
        gemm_body(xr, w + WOFF_REC, sr, nullptr, CC, CC,
                  blockIdx.y * 128, (bx - 32) * 128, EPI_SIGMOID, smem);
    }
}

// ---------------- launch ------------------------------------------------------
extern "C" void kernel_launch(void* const* d_in, const int* in_sizes, int n_in,
                              void* d_out, int out_size) {
    const float* x     = (const float*)d_in[0];
    const float* ln1_w = (const float*)d_in[1];
    const float* ln1_b = (const float*)d_in[2];
    const float* ln2_w = (const float*)d_in[3];
    const float* ln2_b = (const float*)d_in[4];
    const float* atmk  = (const float*)d_in[5];
    const float* atmv  = (const float*)d_in[6];
    const float* atmr  = (const float*)d_in[7];
    const float* tdec  = (const float*)d_in[8];
    const float* tfir  = (const float*)d_in[9];
    const float* Wk    = (const float*)d_in[10];
    const float* Wv    = (const float*)d_in[11];
    const float* Wr    = (const float*)d_in[12];
    const float* Wo    = (const float*)d_in[13];
    const float* ftmk  = (const float*)d_in[14];
    const float* ftmr  = (const float*)d_in[15];
    const float* Wkey  = (const float*)d_in[16];
    const float* Wrec  = (const float*)d_in[17];
    const float* Wval  = (const float*)d_in[18];
    float* out = (float*)d_out;

    float *xk, *xv, *xr, *k, *v, *sr, *kk, *w;
    cudaGetSymbolAddress((void**)&xk, g_xk);
    cudaGetSymbolAddress((void**)&xv, g_xv);
    cudaGetSymbolAddress((void**)&xr, g_xr);
    cudaGetSymbolAddress((void**)&k,  g_k);
    cudaGetSymbolAddress((void**)&v,  g_v);
    cudaGetSymbolAddress((void**)&sr, g_sr);
    cudaGetSymbolAddress((void**)&kk, g_kk);
    cudaGetSymbolAddress((void**)&w,  g_w);

    cudaFuncSetAttribute(tgemm_kernel<EPI_ADDRES>, cudaFuncAttributeMaxDynamicSharedMemorySize, SMEM_DYN);
    cudaFuncSetAttribute(tgemm_kernel<EPI_FINAL>,  cudaFuncAttributeMaxDynamicSharedMemorySize, SMEM_DYN);
    cudaFuncSetAttribute(tgemm_kvr_kernel,         cudaFuncAttributeMaxDynamicSharedMemorySize, SMEM_DYN);
    cudaFuncSetAttribute(tgemm_ff_kernel,          cudaFuncAttributeMaxDynamicSharedMemorySize, SMEM_DYN);

    const dim3 gKVR(8, 128, 3);    // 3072 CTAs: Wk, Wv, Wr batched
    const dim3 gFF(40, 128);       // 5120 CTAs: Wkey (32 cols) + Wrec (8 cols)
    const dim3 gC(8, 128);         // single 1024-CTA GEMMs (Wo, Wval)

    // ---- time-mix (attention) ----
    round_all_kernel<<<13 * 262144 / 256, 256>>>(Wk, Wv, Wr, Wo, Wkey, Wrec, Wval, w);  // 0
    lnmix3_kernel<<<NN, 256>>>(x, ln1_w, ln1_b, atmk, atmv, atmr, xk, xv, xr);           // 1
    tgemm_kvr_kernel<<<gKVR, 256, SMEM_DYN>>>(xk, xv, xr, w, k, v, sr);                  // 2
    wkv_kernel<<<BB * CC / 64, 64>>>(tdec, tfir, k, v, sr, xk);  // xk <- tf32(sr*wkv)    3 (ncu slot)
    tgemm_kernel<EPI_ADDRES><<<gC, 256, SMEM_DYN>>>(xk, w + WOFF_O, out, x, CC, CC);     // 4

    // ---- channel-mix (FFN) ----
    lnmix2_kernel<<<NN, 256>>>(out, ln2_w, ln2_b, ftmk, ftmr, xk, xr);                   // 5
    tgemm_ff_kernel<<<gFF, 256, SMEM_DYN>>>(xk, xr, w, kk, sr);                          // 6
    tgemm_kernel<EPI_FINAL><<<gC, 256, SMEM_DYN>>>(kk, w + WOFF_VAL, out, sr, FF, CC);   // 7
}